// round 9
// baseline (speedup 1.0000x reference)
#include <cuda_runtime.h>
#include <cstdint>
#include <math.h>

// Problem constants
#define BB 4
#define LL 2048
#define DDIM 1024
#define HH 16
#define DH 64
#define CH 128
#define NC 16
#define BH (BB*HH)        // 64
#define BLROWS (BB*LL)    // 8192

// ---------------- scratch (no allocations allowed) ----------------
__device__ float g_q[BB*HH*LL*DH];        // (B,H,L,d)
__device__ float g_k[BB*HH*LL*DH];
__device__ float g_v[BB*HH*LL*DH];
__device__ float g_att[BB*LL*DDIM];       // (B,L,D)
__device__ float g_S[BB*HH*NC*DH*DH];
__device__ float g_z[BB*HH*NC*DH];

// =======================================================================
// TF32 mma.sync GEMM:  C = A @ W^T + bias (A: M x K, W: N x K, row-major)
// CTA tile 128x256, BK=32, 3-stage cp.async, 8 warps (2x4), warp tile 64x64.
// 64x64 warp tile -> 2.33 issue-slots per MMA (was 3.0) on the issue-bound
// scheduler port.  NSPLIT=3: Markidis hi/lo split for Q/K.  NSPLIT=1: V/Wo.
// =======================================================================
#define BM 128
#define BN 256
#define BKK 32
#define KCH (DDIM/BKK)        // 32
#define GSTAGES 3
#define STRD 36               // floats per row (stride % 32 == 4 -> conflict-free frags)
#define A_FLOATS (BM*STRD)    // 4608
#define B_FLOATS (BN*STRD)    // 9216
#define STAGE_FLOATS (A_FLOATS + B_FLOATS)   // 13824
#define SMEM_GEMM_BYTES (GSTAGES*STAGE_FLOATS*4)   // 165888

__device__ __forceinline__ void cp16(uint32_t dst, const void* src) {
    asm volatile("cp.async.cg.shared.global [%0], [%1], 16;" :: "r"(dst), "l"(src));
}
__device__ __forceinline__ uint32_t smem_u32(const void* p) {
    uint32_t a;
    asm("{ .reg .u64 t; cvta.to.shared.u64 t, %1; cvt.u32.u64 %0, t; }" : "=r"(a) : "l"(p));
    return a;
}
__device__ __forceinline__ void cp_commit() {
    asm volatile("cp.async.commit_group;");
}
#define CP_WAIT(n) asm volatile("cp.async.wait_group %0;" :: "n"(n))

__device__ __forceinline__ uint32_t to_tf32(float f) {
    uint32_t r;
    asm("cvt.rna.tf32.f32 %0, %1;" : "=r"(r) : "f"(f));
    return r;
}
__device__ __forceinline__ void split_tf32(float f, uint32_t& hi, uint32_t& lo) {
    hi = to_tf32(f);
    lo = to_tf32(f - __uint_as_float(hi));
}
__device__ __forceinline__ void mma8(float* d, const uint32_t* a, const uint32_t* b) {
    asm volatile(
        "mma.sync.aligned.m16n8k8.row.col.f32.tf32.tf32.f32 "
        "{%0,%1,%2,%3}, {%4,%5,%6,%7}, {%8,%9}, {%0,%1,%2,%3};"
        : "+f"(d[0]), "+f"(d[1]), "+f"(d[2]), "+f"(d[3])
        : "r"(a[0]), "r"(a[1]), "r"(a[2]), "r"(a[3]), "r"(b[0]), "r"(b[1]));
}

// grid: (DDIM/BN, BLROWS/BM) = (4, 64), 256 threads
template<int NSPLIT, int DOSILU, int ATTLAY>
__global__ void __launch_bounds__(256, 1) gemm_tc(
    const float* __restrict__ A, const float* __restrict__ W,
    const float* __restrict__ bias, float* __restrict__ C)
{
    extern __shared__ float sm[];
    const uint32_t sb = smem_u32(sm);
    const int t = threadIdx.x;
    const int lane = t & 31, wid = t >> 5;
    const int wm = wid >> 2, wn = wid & 3;     // 2 x 4 warp grid, warp 64x64
    const int m0 = blockIdx.y * BM;
    const int n0 = blockIdx.x * BN;
    const int g = lane >> 2, tc = lane & 3;

    float acc[4][8][4];
#pragma unroll
    for (int i = 0; i < 4; ++i)
#pragma unroll
        for (int j = 0; j < 8; ++j)
#pragma unroll
            for (int e = 0; e < 4; ++e) acc[i][j][e] = 0.f;

    const float* Abase = A + (size_t)m0 * DDIM;
    const float* Wbase = W + (size_t)n0 * DDIM;

    auto load_chunk = [&](int stage, int kc) {
        const uint32_t abase = sb + (uint32_t)(stage * STAGE_FLOATS) * 4u;
        const uint32_t bbase = abase + A_FLOATS * 4u;
        const int k0 = kc * BKK;
#pragma unroll
        for (int i = 0; i < 4; ++i) {           // A: 1024 x 16B
            int idx = t + 256 * i;
            int row = idx >> 3, seg = idx & 7;
            cp16(abase + (uint32_t)(row * STRD + seg * 4) * 4u,
                 Abase + (size_t)row * DDIM + k0 + seg * 4);
        }
#pragma unroll
        for (int i = 0; i < 8; ++i) {           // B: 2048 x 16B
            int idx = t + 256 * i;
            int row = idx >> 3, seg = idx & 7;
            cp16(bbase + (uint32_t)(row * STRD + seg * 4) * 4u,
                 Wbase + (size_t)row * DDIM + k0 + seg * 4);
        }
    };

    // prologue
#pragma unroll
    for (int s = 0; s < GSTAGES; ++s) { load_chunk(s, s); cp_commit(); }

    int cur = 0;
    for (int kc = 0; kc < KCH; ++kc) {
        CP_WAIT(GSTAGES - 1);
        __syncthreads();

        const float* sA = sm + cur * STAGE_FLOATS;
        const float* sB = sA + A_FLOATS;
#pragma unroll
        for (int ks = 0; ks < 4; ++ks) {
            const int k0 = ks * 8;
            uint32_t bh_[8][2], bl_[8][2];
#pragma unroll
            for (int nt = 0; nt < 8; ++nt) {
                const float* p = sB + (wn * 64 + nt * 8 + g) * STRD + k0 + tc;
                if (NSPLIT == 3) {
                    split_tf32(p[0], bh_[nt][0], bl_[nt][0]);
                    split_tf32(p[4], bh_[nt][1], bl_[nt][1]);
                } else {
                    bh_[nt][0] = to_tf32(p[0]);
                    bh_[nt][1] = to_tf32(p[4]);
                }
            }
#pragma unroll
            for (int mt = 0; mt < 4; ++mt) {
                const float* p = sA + (wm * 64 + mt * 16 + g) * STRD + k0 + tc;
                uint32_t ah[4], al[4];
                if (NSPLIT == 3) {
                    split_tf32(p[0],            ah[0], al[0]);
                    split_tf32(p[8 * STRD],     ah[1], al[1]);
                    split_tf32(p[4],            ah[2], al[2]);
                    split_tf32(p[8 * STRD + 4], ah[3], al[3]);
                } else {
                    ah[0] = to_tf32(p[0]);
                    ah[1] = to_tf32(p[8 * STRD]);
                    ah[2] = to_tf32(p[4]);
                    ah[3] = to_tf32(p[8 * STRD + 4]);
                }
                if (NSPLIT == 3) {
#pragma unroll
                    for (int nt = 0; nt < 8; ++nt)
                        mma8(acc[mt][nt], ah, bl_[nt]);   // hi*lo
#pragma unroll
                    for (int nt = 0; nt < 8; ++nt)
                        mma8(acc[mt][nt], al, bh_[nt]);   // lo*hi
#pragma unroll
                    for (int nt = 0; nt < 8; ++nt)
                        mma8(acc[mt][nt], ah, bh_[nt]);   // hi*hi
                } else {
#pragma unroll
                    for (int nt = 0; nt < 8; ++nt)
                        mma8(acc[mt][nt], ah, bh_[nt]);
                }
            }
        }
        __syncthreads();

        if (kc + GSTAGES < KCH) load_chunk(cur, kc + GSTAGES);
        cp_commit();

        cur = (cur == GSTAGES - 1) ? 0 : cur + 1;
    }

    // ---- epilogue ----
#pragma unroll
    for (int mt = 0; mt < 4; ++mt) {
        const int mrow = m0 + wm * 64 + mt * 16 + g;
#pragma unroll
        for (int nt = 0; nt < 8; ++nt) {
            const int n = n0 + wn * 64 + nt * 8 + tc * 2;
#pragma unroll
            for (int half = 0; half < 2; ++half) {
                const int m = mrow + half * 8;
                float v0 = acc[mt][nt][half * 2 + 0] + bias[n];
                float v1 = acc[mt][nt][half * 2 + 1] + bias[n + 1];
                if (DOSILU) {
                    v0 = v0 / (1.f + expf(-v0));
                    v1 = v1 / (1.f + expf(-v1));
                }
                float2 o; o.x = v0; o.y = v1;
                if (ATTLAY) {
                    int b  = m >> 11;
                    int l  = m & 2047;
                    int h  = n >> 6;
                    int dd = n & 63;
                    *(float2*)&C[(((size_t)(b * HH + h)) * LL + l) * DH + dd] = o;
                } else {
                    *(float2*)&C[(size_t)m * DDIM + n] = o;
                }
            }
        }
    }
}

// ---------------- Phase A: per-chunk kv outer product + ksum ----------------
__global__ __launch_bounds__(256) void chunk_stats()
{
    __shared__ float ks[32*64];
    __shared__ float vs[32*64];

    const int bid = blockIdx.x;
    const float* kb = g_k + (size_t)bid * (CH*DH);
    const float* vb = g_v + (size_t)bid * (CH*DH);
    const int t  = threadIdx.x;
    const int td = t >> 4;
    const int te = t & 15;

    float acc[4][4];
#pragma unroll
    for (int i = 0; i < 4; ++i)
#pragma unroll
        for (int j = 0; j < 4; ++j) acc[i][j] = 0.f;
    float zacc = 0.f;

    for (int cb = 0; cb < 4; ++cb) {
#pragma unroll
        for (int r = 0; r < 2; ++r) {
            int f = t*2 + r;
            *(float4*)&ks[f*4] = *(const float4*)(kb + cb*2048 + f*4);
            *(float4*)&vs[f*4] = *(const float4*)(vb + cb*2048 + f*4);
        }
        __syncthreads();
#pragma unroll 8
        for (int c = 0; c < 32; ++c) {
            float a[4], b[4];
            *(float4*)a = *(const float4*)&ks[c*64 + td*4];
            *(float4*)b = *(const float4*)&vs[c*64 + te*4];
#pragma unroll
            for (int i = 0; i < 4; ++i)
#pragma unroll
                for (int j = 0; j < 4; ++j)
                    acc[i][j] = fmaf(a[i], b[j], acc[i][j]);
        }
        if (t < 64) {
#pragma unroll 8
            for (int c = 0; c < 32; ++c) zacc += ks[c*64 + t];
        }
        __syncthreads();
    }

    float* Sp = g_S + (size_t)bid * (DH*DH);
#pragma unroll
    for (int i = 0; i < 4; ++i)
#pragma unroll
        for (int j = 0; j < 4; ++j)
            Sp[(td*4 + i)*DH + te*4 + j] = acc[i][j];
    if (t < 64) g_z[(size_t)bid*DH + t] = zacc;
}

// ---------------- Phase B: exclusive scan over chunks ----------------
__global__ __launch_bounds__(256) void scan_chunks()
{
    const int bh = blockIdx.x;
    const int t  = threadIdx.x;
    for (int idx = t; idx < DH*DH; idx += 256) {
        float accv = 0.f;
#pragma unroll
        for (int nn = 0; nn < NC; ++nn) {
            float* p = g_S + ((size_t)(bh*NC + nn))*(DH*DH) + idx;
            float tv = *p; *p = accv; accv += tv;
        }
    }
    if (t < DH) {
        float accv = 0.f;
#pragma unroll
        for (int nn = 0; nn < NC; ++nn) {
            float* p = g_z + ((size_t)(bh*NC + nn))*DH + t;
            float tv = *p; *p = accv; accv += tv;
        }
    }
}

// ---------------- Phase C: intra-chunk causal attention (512 threads) ----------------
#define SMEMC_FLOATS (64*136 + 64*136 + 128*64 + 64*64 + 64 + 128 + 128*132)
__global__ __launch_bounds__(512, 1) void intra_chunk()
{
    extern __shared__ float smc[];
    float* qT   = smc;                // [64][136]  (dd-major, padded)
    float* kT   = qT + 64*136;
    float* vs   = kT + 64*136;        // [128][64]
    float* Ss   = vs + 128*64;        // [64][64]
    float* zs   = Ss + 64*64;         // [64]
    float* rden = zs + 64;            // [128]
    float* ms   = rden + 128;         // [128][132]

    const int bid = blockIdx.x;
    const int t   = threadIdx.x;
    const float* qb = g_q + (size_t)bid * (CH*DH);
    const float* kb = g_k + (size_t)bid * (CH*DH);
    const float* vb = g_v + (size_t)bid * (CH*DH);

    {
        int dd = t & 63;
        int ih = t >> 6;              // 0..7
#pragma unroll 4
        for (int ii = 0; ii < 16; ++ii) {
            int i = ih*16 + ii;
            qT[dd*136 + i] = qb[i*DH + dd];
            kT[dd*136 + i] = kb[i*DH + dd];
        }
    }
#pragma unroll
    for (int r = 0; r < 4; ++r) {     // vs: 2048 float4
        int f = t + 512*r;
        *(float4*)&vs[f*4] = *(const float4*)(vb + f*4);
    }
    {
        const float* Sp = g_S + (size_t)bid * (DH*DH);
#pragma unroll
        for (int r = 0; r < 2; ++r) { // Ss: 1024 float4
            int f = t + 512*r;
            *(float4*)&Ss[f*4] = *(const float4*)(Sp + f*4);
        }
    }
    if (t < 64) zs[t] = g_z[(size_t)bid*DH + t];
    __syncthreads();

    // stage 1: scores, 8x4 tile per thread
    {
        const int ty = t >> 5, tx = t & 31;
        const int i0 = ty*8, j0 = tx*4;

        float acc[8][4];
#pragma unroll
        for (int i = 0; i < 8; ++i)
#pragma unroll
            for (int j = 0; j < 4; ++j) acc[i][j] = 0.f;

        if (j0 <= i0 + 7) {           // skip fully-masked tiles
#pragma unroll 4
            for (int c = 0; c < 64; ++c) {
                float a[8], b[4];
                *(float4*)(a)     = *(const float4*)&qT[c*136 + i0];
                *(float4*)(a + 4) = *(const float4*)&qT[c*136 + i0 + 4];
                *(float4*)(b)     = *(const float4*)&kT[c*136 + j0];
#pragma unroll
                for (int i = 0; i < 8; ++i)
#pragma unroll
                    for (int j = 0; j < 4; ++j)
                        acc[i][j] = fmaf(a[i], b[j], acc[i][j]);
            }
        }
#pragma unroll
        for (int i = 0; i < 8; ++i)
#pragma unroll
            for (int j = 0; j < 4; ++j)
                ms[(i0+i)*132 + j0 + j] = (j0 + j <= i0 + i) ? acc[i][j] : 0.f;
    }
    __syncthreads();

    // denominator per row = rowsum(masked scores) + q.z  (4 threads/row)
    if (t < 512) {
        const int i = t >> 2, part = t & 3;
        float s = 0.f;
        const int jb = part * 32;
#pragma unroll 8
        for (int j = 0; j < 32; ++j) s += ms[i*132 + jb + j];
        const int db = part * 16;
#pragma unroll 8
        for (int dd = 0; dd < 16; ++dd) s += qT[(db+dd)*136 + i] * zs[db+dd];
        s += __shfl_down_sync(0xFFFFFFFF, s, 2);
        s += __shfl_down_sync(0xFFFFFFFF, s, 1);
        if (part == 0) rden[i] = 1.f / fmaxf(s, 0.001f);
    }
    __syncthreads();

    // stage 2: out[i][e] = sum_j ms[i][j]*v[j][e] + sum_dd q[i][dd]*S[dd][e]
    {
        const int i0 = (t >> 4) * 4;      // 0..124
        const int e0 = (t & 15) * 4;      // 0..60
        float o[4][4];
#pragma unroll
        for (int i = 0; i < 4; ++i)
#pragma unroll
            for (int e = 0; e < 4; ++e) o[i][e] = 0.f;

#pragma unroll 4
        for (int j = 0; j < 128; ++j) {
            float vf[4];
            *(float4*)vf = *(const float4*)&vs[j*64 + e0];
#pragma unroll
            for (int i = 0; i < 4; ++i) {
                float mv = ms[(i0+i)*132 + j];
                o[i][0] = fmaf(mv, vf[0], o[i][0]);
                o[i][1] = fmaf(mv, vf[1], o[i][1]);
                o[i][2] = fmaf(mv, vf[2], o[i][2]);
                o[i][3] = fmaf(mv, vf[3], o[i][3]);
            }
        }
#pragma unroll 4
        for (int dd = 0; dd < 64; ++dd) {
            float sf[4];
            *(float4*)sf = *(const float4*)&Ss[dd*64 + e0];
#pragma unroll
            for (int i = 0; i < 4; ++i) {
                float qv = qT[dd*136 + i0 + i];
                o[i][0] = fmaf(qv, sf[0], o[i][0]);
                o[i][1] = fmaf(qv, sf[1], o[i][1]);
                o[i][2] = fmaf(qv, sf[2], o[i][2]);
                o[i][3] = fmaf(qv, sf[3], o[i][3]);
            }
        }

        const int bh = bid >> 4, n = bid & 15;
        const int b = bh >> 4, h = bh & 15;
#pragma unroll
        for (int i = 0; i < 4; ++i) {
            float rd = rden[i0 + i];
            int l = n*CH + i0 + i;
            float4 ov;
            ov.x = o[i][0] * rd; ov.y = o[i][1] * rd;
            ov.z = o[i][2] * rd; ov.w = o[i][3] * rd;
            *(float4*)&g_att[((size_t)(b*LL + l))*DDIM + h*DH + e0] = ov;
        }
    }
}

// ---------------- launch ----------------
extern "C" void kernel_launch(void* const* d_in, const int* in_sizes, int n_in,
                              void* d_out, int out_size)
{
    const float* x  = (const float*)d_in[0];
    const float* Wq = (const float*)d_in[1];
    const float* bq = (const float*)d_in[2];
    const float* Wk = (const float*)d_in[3];
    const float* bk = (const float*)d_in[4];
    const float* Wv = (const float*)d_in[5];
    const float* bv = (const float*)d_in[6];
    const float* Wo = (const float*)d_in[7];
    const float* bo = (const float*)d_in[8];
    float* out = (float*)d_out;

    float *qp, *kp, *vp, *attp;
    cudaGetSymbolAddress((void**)&qp,  g_q);
    cudaGetSymbolAddress((void**)&kp,  g_k);
    cudaGetSymbolAddress((void**)&vp,  g_v);
    cudaGetSymbolAddress((void**)&attp, g_att);

    cudaFuncSetAttribute(gemm_tc<3,1,1>, cudaFuncAttributeMaxDynamicSharedMemorySize,
                         SMEM_GEMM_BYTES);
    cudaFuncSetAttribute(gemm_tc<1,0,1>, cudaFuncAttributeMaxDynamicSharedMemorySize,
                         SMEM_GEMM_BYTES);
    cudaFuncSetAttribute(gemm_tc<1,0,0>, cudaFuncAttributeMaxDynamicSharedMemorySize,
                         SMEM_GEMM_BYTES);
    cudaFuncSetAttribute(intra_chunk, cudaFuncAttributeMaxDynamicSharedMemorySize,
                         SMEMC_FLOATS * (int)sizeof(float));

    // One-time stream/event setup (no device memory involved)
    static cudaStream_t sK = nullptr, sV = nullptr;
    static cudaEvent_t eFork, eV, eQ, eAtt;
    if (sK == nullptr) {
        cudaStreamCreateWithFlags(&sK, cudaStreamNonBlocking);
        cudaStreamCreateWithFlags(&sV, cudaStreamNonBlocking);
        cudaEventCreateWithFlags(&eFork, cudaEventDisableTiming);
        cudaEventCreateWithFlags(&eV,    cudaEventDisableTiming);
        cudaEventCreateWithFlags(&eQ,    cudaEventDisableTiming);
        cudaEventCreateWithFlags(&eAtt,  cudaEventDisableTiming);
    }

    dim3 gg(DDIM/BN, BLROWS/BM);   // (4, 64)
    dim3 bb(256);

    // Fork from the origin stream so sK/sV join the capture.
    cudaEventRecord(eFork, 0);
    cudaStreamWaitEvent(sK, eFork, 0);
    cudaStreamWaitEvent(sV, eFork, 0);

    // K, V issued first -> work distributor fills SMs with them first.
    gemm_tc<3,1,1><<<gg, bb, SMEM_GEMM_BYTES, sK>>>(x, Wk, bk, kp);
    gemm_tc<1,0,1><<<gg, bb, SMEM_GEMM_BYTES, sV>>>(x, Wv, bv, vp);
    cudaEventRecord(eV, sV);

    // Q on origin stream: starts as K/V drain; runs concurrent with stats/scan.
    gemm_tc<3,1,1><<<gg, bb, SMEM_GEMM_BYTES>>>(x, Wq, bq, qp);
    cudaEventRecord(eQ, 0);

    // stats+scan on sK after K (stream-ordered) and V (event).
    cudaStreamWaitEvent(sK, eV, 0);
    chunk_stats<<<BH*NC, 256, 0, sK>>>();
    scan_chunks<<<BH, 256, 0, sK>>>();

    // intra needs Q as well.
    cudaStreamWaitEvent(sK, eQ, 0);
    intra_chunk<<<BH*NC, 512, SMEMC_FLOATS * sizeof(float), sK>>>();
    cudaEventRecord(eAtt, sK);

    // Wo joins back on the origin stream.
    cudaStreamWaitEvent(0, eAtt, 0);
    gemm_tc<1,0,0><<<gg, bb, SMEM_GEMM_BYTES>>>(attp, Wo, bo, out);
}

// round 10
// speedup vs baseline: 1.0306x; 1.0306x over previous
#include <cuda_runtime.h>
#include <cstdint>
#include <math.h>

// Problem constants
#define BB 4
#define LL 2048
#define DDIM 1024
#define HH 16
#define DH 64
#define CH 128
#define NC 16
#define BH (BB*HH)        // 64
#define BLROWS (BB*LL)    // 8192

// ---------------- scratch (no allocations allowed) ----------------
__device__ float g_q[BB*HH*LL*DH];        // (B,H,L,d)
__device__ float g_k[BB*HH*LL*DH];
__device__ float g_v[BB*HH*LL*DH];
__device__ float g_att[BB*LL*DDIM];       // (B,L,D)
__device__ float g_S[BB*HH*NC*DH*DH];
__device__ float g_z[BB*HH*NC*DH];

// =======================================================================
// TF32 mma.sync GEMM:  C = A @ W^T + bias (A: M x K, W: N x K, row-major)
// BIGN=0: CTA 128x128, warp 64x32, 2 CTA/SM  (used for NSPLIT=3 Q/K — high
//         register pressure, needs co-resident CTA for latency hiding)
// BIGN=1: CTA 128x256, warp 64x64, 1 CTA/SM  (used for NSPLIT=1 V/Wo —
//         3.0 instead of 4.0 issue-slots per MMA, regs fit)
// moff: global row offset (batch-half splitting for finer stream overlap)
// =======================================================================
#define BM 128
#define BKK 32
#define KCH (DDIM/BKK)        // 32
#define GSTAGES 3
#define STRD 36               // floats per row (stride % 32 == 4 -> conflict-free frags)
#define A_FLOATS (BM*STRD)    // 4608
#define SMEM_S ((GSTAGES*(A_FLOATS + 128*STRD))*4)   // 110592 (BIGN=0)
#define SMEM_B ((GSTAGES*(A_FLOATS + 256*STRD))*4)   // 165888 (BIGN=1)

__device__ __forceinline__ void cp16(uint32_t dst, const void* src) {
    asm volatile("cp.async.cg.shared.global [%0], [%1], 16;" :: "r"(dst), "l"(src));
}
__device__ __forceinline__ uint32_t smem_u32(const void* p) {
    uint32_t a;
    asm("{ .reg .u64 t; cvta.to.shared.u64 t, %1; cvt.u32.u64 %0, t; }" : "=r"(a) : "l"(p));
    return a;
}
__device__ __forceinline__ void cp_commit() {
    asm volatile("cp.async.commit_group;");
}
#define CP_WAIT(n) asm volatile("cp.async.wait_group %0;" :: "n"(n))

__device__ __forceinline__ uint32_t to_tf32(float f) {
    uint32_t r;
    asm("cvt.rna.tf32.f32 %0, %1;" : "=r"(r) : "f"(f));
    return r;
}
__device__ __forceinline__ void split_tf32(float f, uint32_t& hi, uint32_t& lo) {
    hi = to_tf32(f);
    lo = to_tf32(f - __uint_as_float(hi));
}
__device__ __forceinline__ void mma8(float* d, const uint32_t* a, const uint32_t* b) {
    asm volatile(
        "mma.sync.aligned.m16n8k8.row.col.f32.tf32.tf32.f32 "
        "{%0,%1,%2,%3}, {%4,%5,%6,%7}, {%8,%9}, {%0,%1,%2,%3};"
        : "+f"(d[0]), "+f"(d[1]), "+f"(d[2]), "+f"(d[3])
        : "r"(a[0]), "r"(a[1]), "r"(a[2]), "r"(a[3]), "r"(b[0]), "r"(b[1]));
}

template<int NSPLIT, int DOSILU, int ATTLAY, int BIGN>
__global__ void __launch_bounds__(256, BIGN ? 1 : 2) gemm_tc(
    const float* __restrict__ A, const float* __restrict__ W,
    const float* __restrict__ bias, float* __restrict__ C, int moff)
{
    constexpr int BNT = BIGN ? 256 : 128;     // CTA N-tile
    constexpr int NTC = BIGN ? 8 : 4;         // n-subtiles per warp
    constexpr int B_FLOATS = BNT * STRD;
    constexpr int STAGE_FLOATS = A_FLOATS + B_FLOATS;

    extern __shared__ float sm[];
    const uint32_t sb = smem_u32(sm);
    const int t = threadIdx.x;
    const int lane = t & 31, wid = t >> 5;
    const int wm = wid >> 2, wn = wid & 3;     // 2 x 4 warp grid
    const int m0 = blockIdx.y * BM;
    const int n0 = blockIdx.x * BNT;
    const int g = lane >> 2, tc = lane & 3;

    float acc[4][NTC][4];
#pragma unroll
    for (int i = 0; i < 4; ++i)
#pragma unroll
        for (int j = 0; j < NTC; ++j)
#pragma unroll
            for (int e = 0; e < 4; ++e) acc[i][j][e] = 0.f;

    const float* Abase = A + (size_t)(moff + m0) * DDIM;
    const float* Wbase = W + (size_t)n0 * DDIM;

    auto load_chunk = [&](int stage, int kc) {
        const uint32_t abase = sb + (uint32_t)(stage * STAGE_FLOATS) * 4u;
        const uint32_t bbase = abase + A_FLOATS * 4u;
        const int k0 = kc * BKK;
#pragma unroll
        for (int i = 0; i < 4; ++i) {             // A: 1024 x 16B
            int idx = t + 256 * i;
            int row = idx >> 3, seg = idx & 7;
            cp16(abase + (uint32_t)(row * STRD + seg * 4) * 4u,
                 Abase + (size_t)row * DDIM + k0 + seg * 4);
        }
#pragma unroll
        for (int i = 0; i < BNT / 32; ++i) {      // B: BNT*8 x 16B
            int idx = t + 256 * i;
            int row = idx >> 3, seg = idx & 7;
            cp16(bbase + (uint32_t)(row * STRD + seg * 4) * 4u,
                 Wbase + (size_t)row * DDIM + k0 + seg * 4);
        }
    };

    // prologue
#pragma unroll
    for (int s = 0; s < GSTAGES; ++s) { load_chunk(s, s); cp_commit(); }

    int cur = 0;
    for (int kc = 0; kc < KCH; ++kc) {
        CP_WAIT(GSTAGES - 1);
        __syncthreads();

        const float* sA = sm + cur * STAGE_FLOATS;
        const float* sB = sA + A_FLOATS;
#pragma unroll
        for (int ks = 0; ks < 4; ++ks) {
            const int k0 = ks * 8;
            uint32_t bh_[NTC][2], bl_[NTC][2];
#pragma unroll
            for (int nt = 0; nt < NTC; ++nt) {
                const float* p = sB + (wn * (8 * NTC) + nt * 8 + g) * STRD + k0 + tc;
                if (NSPLIT == 3) {
                    split_tf32(p[0], bh_[nt][0], bl_[nt][0]);
                    split_tf32(p[4], bh_[nt][1], bl_[nt][1]);
                } else {
                    bh_[nt][0] = to_tf32(p[0]);
                    bh_[nt][1] = to_tf32(p[4]);
                }
            }
            if (NSPLIT == 3) {
                // mt pairs, term-major (R8-identical math & order)
#pragma unroll
                for (int mtg = 0; mtg < 2; ++mtg) {
                    uint32_t ah[2][4], al[2][4];
#pragma unroll
                    for (int mi = 0; mi < 2; ++mi) {
                        const int mt = mtg * 2 + mi;
                        const float* p = sA + (wm * 64 + mt * 16 + g) * STRD + k0 + tc;
                        split_tf32(p[0],            ah[mi][0], al[mi][0]);
                        split_tf32(p[8 * STRD],     ah[mi][1], al[mi][1]);
                        split_tf32(p[4],            ah[mi][2], al[mi][2]);
                        split_tf32(p[8 * STRD + 4], ah[mi][3], al[mi][3]);
                    }
#pragma unroll
                    for (int mi = 0; mi < 2; ++mi)
#pragma unroll
                        for (int nt = 0; nt < NTC; ++nt)
                            mma8(acc[mtg * 2 + mi][nt], ah[mi], bl_[nt]);  // hi*lo
#pragma unroll
                    for (int mi = 0; mi < 2; ++mi)
#pragma unroll
                        for (int nt = 0; nt < NTC; ++nt)
                            mma8(acc[mtg * 2 + mi][nt], al[mi], bh_[nt]);  // lo*hi
#pragma unroll
                    for (int mi = 0; mi < 2; ++mi)
#pragma unroll
                        for (int nt = 0; nt < NTC; ++nt)
                            mma8(acc[mtg * 2 + mi][nt], ah[mi], bh_[nt]);  // hi*hi
                }
            } else {
#pragma unroll
                for (int mt = 0; mt < 4; ++mt) {
                    const float* p = sA + (wm * 64 + mt * 16 + g) * STRD + k0 + tc;
                    uint32_t ah[4];
                    ah[0] = to_tf32(p[0]);
                    ah[1] = to_tf32(p[8 * STRD]);
                    ah[2] = to_tf32(p[4]);
                    ah[3] = to_tf32(p[8 * STRD + 4]);
#pragma unroll
                    for (int nt = 0; nt < NTC; ++nt)
                        mma8(acc[mt][nt], ah, bh_[nt]);
                }
            }
        }
        __syncthreads();

        if (kc + GSTAGES < KCH) load_chunk(cur, kc + GSTAGES);
        cp_commit();

        cur = (cur == GSTAGES - 1) ? 0 : cur + 1;
    }

    // ---- epilogue ----
#pragma unroll
    for (int mt = 0; mt < 4; ++mt) {
        const int mrow = moff + m0 + wm * 64 + mt * 16 + g;
#pragma unroll
        for (int nt = 0; nt < NTC; ++nt) {
            const int n = n0 + wn * (8 * NTC) + nt * 8 + tc * 2;
#pragma unroll
            for (int half = 0; half < 2; ++half) {
                const int m = mrow + half * 8;
                float v0 = acc[mt][nt][half * 2 + 0] + bias[n];
                float v1 = acc[mt][nt][half * 2 + 1] + bias[n + 1];
                if (DOSILU) {
                    v0 = v0 / (1.f + expf(-v0));
                    v1 = v1 / (1.f + expf(-v1));
                }
                float2 o; o.x = v0; o.y = v1;
                if (ATTLAY) {
                    int b  = m >> 11;
                    int l  = m & 2047;
                    int h  = n >> 6;
                    int dd = n & 63;
                    *(float2*)&C[(((size_t)(b * HH + h)) * LL + l) * DH + dd] = o;
                } else {
                    *(float2*)&C[(size_t)m * DDIM + n] = o;
                }
            }
        }
    }
}

// ---------------- Phase A: per-chunk kv outer product + ksum ----------------
__global__ __launch_bounds__(256) void chunk_stats()
{
    __shared__ float ks[32*64];
    __shared__ float vs[32*64];

    const int bid = blockIdx.x;
    const float* kb = g_k + (size_t)bid * (CH*DH);
    const float* vb = g_v + (size_t)bid * (CH*DH);
    const int t  = threadIdx.x;
    const int td = t >> 4;
    const int te = t & 15;

    float acc[4][4];
#pragma unroll
    for (int i = 0; i < 4; ++i)
#pragma unroll
        for (int j = 0; j < 4; ++j) acc[i][j] = 0.f;
    float zacc = 0.f;

    for (int cb = 0; cb < 4; ++cb) {
#pragma unroll
        for (int r = 0; r < 2; ++r) {
            int f = t*2 + r;
            *(float4*)&ks[f*4] = *(const float4*)(kb + cb*2048 + f*4);
            *(float4*)&vs[f*4] = *(const float4*)(vb + cb*2048 + f*4);
        }
        __syncthreads();
#pragma unroll 8
        for (int c = 0; c < 32; ++c) {
            float a[4], b[4];
            *(float4*)a = *(const float4*)&ks[c*64 + td*4];
            *(float4*)b = *(const float4*)&vs[c*64 + te*4];
#pragma unroll
            for (int i = 0; i < 4; ++i)
#pragma unroll
                for (int j = 0; j < 4; ++j)
                    acc[i][j] = fmaf(a[i], b[j], acc[i][j]);
        }
        if (t < 64) {
#pragma unroll 8
            for (int c = 0; c < 32; ++c) zacc += ks[c*64 + t];
        }
        __syncthreads();
    }

    float* Sp = g_S + (size_t)bid * (DH*DH);
#pragma unroll
    for (int i = 0; i < 4; ++i)
#pragma unroll
        for (int j = 0; j < 4; ++j)
            Sp[(td*4 + i)*DH + te*4 + j] = acc[i][j];
    if (t < 64) g_z[(size_t)bid*DH + t] = zacc;
}

// ---------------- Phase B: exclusive scan over chunks ----------------
__global__ __launch_bounds__(256) void scan_chunks()
{
    const int bh = blockIdx.x;
    const int t  = threadIdx.x;
    for (int idx = t; idx < DH*DH; idx += 256) {
        float accv = 0.f;
#pragma unroll
        for (int nn = 0; nn < NC; ++nn) {
            float* p = g_S + ((size_t)(bh*NC + nn))*(DH*DH) + idx;
            float tv = *p; *p = accv; accv += tv;
        }
    }
    if (t < DH) {
        float accv = 0.f;
#pragma unroll
        for (int nn = 0; nn < NC; ++nn) {
            float* p = g_z + ((size_t)(bh*NC + nn))*DH + t;
            float tv = *p; *p = accv; accv += tv;
        }
    }
}

// ---------------- Phase C: intra-chunk causal attention (512 threads) ----------------
#define SMEMC_FLOATS (64*136 + 64*136 + 128*64 + 64*64 + 64 + 128 + 128*132)
__global__ __launch_bounds__(512, 1) void intra_chunk(int bid_off)
{
    extern __shared__ float smc[];
    float* qT   = smc;                // [64][136]  (dd-major, padded)
    float* kT   = qT + 64*136;
    float* vs   = kT + 64*136;        // [128][64]
    float* Ss   = vs + 128*64;        // [64][64]
    float* zs   = Ss + 64*64;         // [64]
    float* rden = zs + 64;            // [128]
    float* ms   = rden + 128;         // [128][132]

    const int bid = blockIdx.x + bid_off;
    const int t   = threadIdx.x;
    const float* qb = g_q + (size_t)bid * (CH*DH);
    const float* kb = g_k + (size_t)bid * (CH*DH);
    const float* vb = g_v + (size_t)bid * (CH*DH);

    {
        int dd = t & 63;
        int ih = t >> 6;              // 0..7
#pragma unroll 4
        for (int ii = 0; ii < 16; ++ii) {
            int i = ih*16 + ii;
            qT[dd*136 + i] = qb[i*DH + dd];
            kT[dd*136 + i] = kb[i*DH + dd];
        }
    }
#pragma unroll
    for (int r = 0; r < 4; ++r) {     // vs: 2048 float4
        int f = t + 512*r;
        *(float4*)&vs[f*4] = *(const float4*)(vb + f*4);
    }
    {
        const float* Sp = g_S + (size_t)bid * (DH*DH);
#pragma unroll
        for (int r = 0; r < 2; ++r) { // Ss: 1024 float4
            int f = t + 512*r;
            *(float4*)&Ss[f*4] = *(const float4*)(Sp + f*4);
        }
    }
    if (t < 64) zs[t] = g_z[(size_t)bid*DH + t];
    __syncthreads();

    // stage 1: scores, 8x4 tile per thread
    {
        const int ty = t >> 5, tx = t & 31;
        const int i0 = ty*8, j0 = tx*4;

        float acc[8][4];
#pragma unroll
        for (int i = 0; i < 8; ++i)
#pragma unroll
            for (int j = 0; j < 4; ++j) acc[i][j] = 0.f;

        if (j0 <= i0 + 7) {           // skip fully-masked tiles
#pragma unroll 4
            for (int c = 0; c < 64; ++c) {
                float a[8], b[4];
                *(float4*)(a)     = *(const float4*)&qT[c*136 + i0];
                *(float4*)(a + 4) = *(const float4*)&qT[c*136 + i0 + 4];
                *(float4*)(b)     = *(const float4*)&kT[c*136 + j0];
#pragma unroll
                for (int i = 0; i < 8; ++i)
#pragma unroll
                    for (int j = 0; j < 4; ++j)
                        acc[i][j] = fmaf(a[i], b[j], acc[i][j]);
            }
        }
#pragma unroll
        for (int i = 0; i < 8; ++i)
#pragma unroll
            for (int j = 0; j < 4; ++j)
                ms[(i0+i)*132 + j0 + j] = (j0 + j <= i0 + i) ? acc[i][j] : 0.f;
    }
    __syncthreads();

    // denominator per row = rowsum(masked scores) + q.z  (4 threads/row)
    if (t < 512) {
        const int i = t >> 2, part = t & 3;
        float s = 0.f;
        const int jb = part * 32;
#pragma unroll 8
        for (int j = 0; j < 32; ++j) s += ms[i*132 + jb + j];
        const int db = part * 16;
#pragma unroll 8
        for (int dd = 0; dd < 16; ++dd) s += qT[(db+dd)*136 + i] * zs[db+dd];
        s += __shfl_down_sync(0xFFFFFFFF, s, 2);
        s += __shfl_down_sync(0xFFFFFFFF, s, 1);
        if (part == 0) rden[i] = 1.f / fmaxf(s, 0.001f);
    }
    __syncthreads();

    // stage 2: out[i][e] = sum_j ms[i][j]*v[j][e] + sum_dd q[i][dd]*S[dd][e]
    {
        const int i0 = (t >> 4) * 4;      // 0..124
        const int e0 = (t & 15) * 4;      // 0..60
        float o[4][4];
#pragma unroll
        for (int i = 0; i < 4; ++i)
#pragma unroll
            for (int e = 0; e < 4; ++e) o[i][e] = 0.f;

#pragma unroll 4
        for (int j = 0; j < 128; ++j) {
            float vf[4];
            *(float4*)vf = *(const float4*)&vs[j*64 + e0];
#pragma unroll
            for (int i = 0; i < 4; ++i) {
                float mv = ms[(i0+i)*132 + j];
                o[i][0] = fmaf(mv, vf[0], o[i][0]);
                o[i][1] = fmaf(mv, vf[1], o[i][1]);
                o[i][2] = fmaf(mv, vf[2], o[i][2]);
                o[i][3] = fmaf(mv, vf[3], o[i][3]);
            }
        }
#pragma unroll 4
        for (int dd = 0; dd < 64; ++dd) {
            float sf[4];
            *(float4*)sf = *(const float4*)&Ss[dd*64 + e0];
#pragma unroll
            for (int i = 0; i < 4; ++i) {
                float qv = qT[dd*136 + i0 + i];
                o[i][0] = fmaf(qv, sf[0], o[i][0]);
                o[i][1] = fmaf(qv, sf[1], o[i][1]);
                o[i][2] = fmaf(qv, sf[2], o[i][2]);
                o[i][3] = fmaf(qv, sf[3], o[i][3]);
            }
        }

        const int bh = bid >> 4, n = bid & 15;
        const int b = bh >> 4, h = bh & 15;
#pragma unroll
        for (int i = 0; i < 4; ++i) {
            float rd = rden[i0 + i];
            int l = n*CH + i0 + i;
            float4 ov;
            ov.x = o[i][0] * rd; ov.y = o[i][1] * rd;
            ov.z = o[i][2] * rd; ov.w = o[i][3] * rd;
            *(float4*)&g_att[((size_t)(b*LL + l))*DDIM + h*DH + e0] = ov;
        }
    }
}

// ---------------- launch ----------------
extern "C" void kernel_launch(void* const* d_in, const int* in_sizes, int n_in,
                              void* d_out, int out_size)
{
    const float* x  = (const float*)d_in[0];
    const float* Wq = (const float*)d_in[1];
    const float* bq = (const float*)d_in[2];
    const float* Wk = (const float*)d_in[3];
    const float* bk = (const float*)d_in[4];
    const float* Wv = (const float*)d_in[5];
    const float* bv = (const float*)d_in[6];
    const float* Wo = (const float*)d_in[7];
    const float* bo = (const float*)d_in[8];
    float* out = (float*)d_out;

    float *qp, *kp, *vp, *attp;
    cudaGetSymbolAddress((void**)&qp,  g_q);
    cudaGetSymbolAddress((void**)&kp,  g_k);
    cudaGetSymbolAddress((void**)&vp,  g_v);
    cudaGetSymbolAddress((void**)&attp, g_att);

    cudaFuncSetAttribute(gemm_tc<3,1,1,0>, cudaFuncAttributeMaxDynamicSharedMemorySize, SMEM_S);
    cudaFuncSetAttribute(gemm_tc<1,0,1,1>, cudaFuncAttributeMaxDynamicSharedMemorySize, SMEM_B);
    cudaFuncSetAttribute(gemm_tc<1,0,0,1>, cudaFuncAttributeMaxDynamicSharedMemorySize, SMEM_B);
    cudaFuncSetAttribute(intra_chunk, cudaFuncAttributeMaxDynamicSharedMemorySize,
                         SMEMC_FLOATS * (int)sizeof(float));

    // One-time stream/event setup (no device memory involved)
    static cudaStream_t sK = nullptr, sV = nullptr;
    static cudaEvent_t eFork, eV, eQA, eQB, eIA, eIB;
    if (sK == nullptr) {
        cudaStreamCreateWithFlags(&sK, cudaStreamNonBlocking);
        cudaStreamCreateWithFlags(&sV, cudaStreamNonBlocking);
        cudaEventCreateWithFlags(&eFork, cudaEventDisableTiming);
        cudaEventCreateWithFlags(&eV,    cudaEventDisableTiming);
        cudaEventCreateWithFlags(&eQA,   cudaEventDisableTiming);
        cudaEventCreateWithFlags(&eQB,   cudaEventDisableTiming);
        cudaEventCreateWithFlags(&eIA,   cudaEventDisableTiming);
        cudaEventCreateWithFlags(&eIB,   cudaEventDisableTiming);
    }

    dim3 bbg(256);
    dim3 gg_k(8, 64);     // K full   (128x128 tiles)
    dim3 gg_qh(8, 32);    // Q half
    dim3 gg_v(4, 64);     // V full   (128x256 tiles)
    dim3 gg_wh(4, 32);    // Wo half  (128x256 tiles)

    // Fork from the origin stream so sK/sV join the capture.
    cudaEventRecord(eFork, 0);
    cudaStreamWaitEvent(sK, eFork, 0);
    cudaStreamWaitEvent(sV, eFork, 0);

    // K and V fill the machine first.
    gemm_tc<3,1,1,0><<<gg_k, bbg, SMEM_S, sK>>>(x, Wk, bk, kp, 0);
    gemm_tc<1,0,1,1><<<gg_v, bbg, SMEM_B, sV>>>(x, Wv, bv, vp, 0);
    cudaEventRecord(eV, sV);

    // Q in two batch-halves on the origin stream.
    gemm_tc<3,1,1,0><<<gg_qh, bbg, SMEM_S>>>(x, Wq, bq, qp, 0);
    cudaEventRecord(eQA, 0);
    gemm_tc<3,1,1,0><<<gg_qh, bbg, SMEM_S>>>(x, Wq, bq, qp, 4096);
    cudaEventRecord(eQB, 0);

    // stats+scan on sK after K (stream-ordered) and V (event).
    cudaStreamWaitEvent(sK, eV, 0);
    chunk_stats<<<BH*NC, 256, 0, sK>>>();
    scan_chunks<<<BH, 256, 0, sK>>>();

    // intra halves: A (b 0,1) after Q_A — overlaps Q_B; B after Q_B.
    cudaStreamWaitEvent(sK, eQA, 0);
    intra_chunk<<<512, 512, SMEMC_FLOATS * sizeof(float), sK>>>(0);
    cudaEventRecord(eIA, sK);
    cudaStreamWaitEvent(sK, eQB, 0);
    intra_chunk<<<512, 512, SMEMC_FLOATS * sizeof(float), sK>>>(512);
    cudaEventRecord(eIB, sK);

    // Wo halves on origin: A overlaps intra_B.
    cudaStreamWaitEvent(0, eIA, 0);
    gemm_tc<1,0,0,1><<<gg_wh, bbg, SMEM_B>>>(attp, Wo, bo, out, 0);
    cudaStreamWaitEvent(0, eIB, 0);
    gemm_tc<1,0,0,1><<<gg_wh, bbg, SMEM_B>>>(attp, Wo, bo, out, 4096);
}

// round 12
// speedup vs baseline: 1.2578x; 1.2204x over previous
#include <cuda_runtime.h>
#include <cstdint>
#include <math.h>

// Problem constants
#define BB 4
#define LL 2048
#define DDIM 1024
#define HH 16
#define DH 64
#define CH 128
#define NC 16
#define BH (BB*HH)        // 64
#define BLROWS (BB*LL)    // 8192

// ---------------- scratch (no allocations allowed) ----------------
__device__ float g_q[BB*HH*LL*DH];        // (B,H,L,d)
__device__ float g_k[BB*HH*LL*DH];
__device__ float g_v[BB*HH*LL*DH];
__device__ float g_att[BB*LL*DDIM];       // (B,L,D)
__device__ float g_S[BB*HH*NC*DH*DH];
__device__ float g_z[BB*HH*NC*DH];

// =======================================================================
// Mixed-mode tensor-core GEMM:  C = A @ W^T + bias
// Tile 128x128, BK=32, 3-stage cp.async, 8 warps (2x4), warp 64x32, 2 CTA/SM.
// MODE 2: fp16 m16n8k16 hi/lo split (3 terms, eps ~2^-21) — Q/K (den path,
//         range-safe inputs |v|<~6)
// MODE 1: fp16 m16n8k16 single — V (range-safe)
// MODE 0: tf32 m16n8k8 single — Wo (attention output can reach ~1e5;
//         fp16 fragments overflow -> NaN, tf32 keeps fp32 exponent range)
// =======================================================================
#define BM 128
#define BN 128
#define BKK 32
#define KCH (DDIM/BKK)        // 32
#define GSTAGES 3
#define STRD 36               // floats per row
#define A_FLOATS (BM*STRD)    // 4608
#define STAGE_FLOATS (2*A_FLOATS)   // 9216 (A then B)
#define SMEM_GEMM_BYTES (GSTAGES*STAGE_FLOATS*4)   // 110592

__device__ __forceinline__ void cp16(uint32_t dst, const void* src) {
    asm volatile("cp.async.cg.shared.global [%0], [%1], 16;" :: "r"(dst), "l"(src));
}
__device__ __forceinline__ uint32_t smem_u32(const void* p) {
    uint32_t a;
    asm("{ .reg .u64 t; cvta.to.shared.u64 t, %1; cvt.u32.u64 %0, t; }" : "=r"(a) : "l"(p));
    return a;
}
__device__ __forceinline__ void cp_commit() {
    asm volatile("cp.async.commit_group;");
}
#define CP_WAIT(n) asm volatile("cp.async.wait_group %0;" :: "n"(n))

// ---- fp16 helpers ----
// pack two f32 into f16x2: low half = 'lo' (k even), high half = 'hi' (k odd)
__device__ __forceinline__ uint32_t packh2(float hi, float lo) {
    uint32_t r;
    asm("cvt.rn.f16x2.f32 %0, %1, %2;" : "=r"(r) : "f"(hi), "f"(lo));
    return r;
}
// h = v truncated to 10 mantissa bits (exact in fp16 for normal range); l = v-h
__device__ __forceinline__ void split_h(float v, float& h, float& l) {
    h = __uint_as_float(__float_as_uint(v) & 0xFFFFE000u);
    l = v - h;
}
__device__ __forceinline__ void mma16(float* d, const uint32_t* a, const uint32_t* b) {
    asm volatile(
        "mma.sync.aligned.m16n8k16.row.col.f32.f16.f16.f32 "
        "{%0,%1,%2,%3}, {%4,%5,%6,%7}, {%8,%9}, {%0,%1,%2,%3};"
        : "+f"(d[0]), "+f"(d[1]), "+f"(d[2]), "+f"(d[3])
        : "r"(a[0]), "r"(a[1]), "r"(a[2]), "r"(a[3]), "r"(b[0]), "r"(b[1]));
}
// ---- tf32 helpers ----
__device__ __forceinline__ uint32_t to_tf32(float f) {
    uint32_t r;
    asm("cvt.rna.tf32.f32 %0, %1;" : "=r"(r) : "f"(f));
    return r;
}
__device__ __forceinline__ void mma8(float* d, const uint32_t* a, const uint32_t* b) {
    asm volatile(
        "mma.sync.aligned.m16n8k8.row.col.f32.tf32.tf32.f32 "
        "{%0,%1,%2,%3}, {%4,%5,%6,%7}, {%8,%9}, {%0,%1,%2,%3};"
        : "+f"(d[0]), "+f"(d[1]), "+f"(d[2]), "+f"(d[3])
        : "r"(a[0]), "r"(a[1]), "r"(a[2]), "r"(a[3]), "r"(b[0]), "r"(b[1]));
}

// grid: (DDIM/BN, BLROWS/BM) = (8, 64), 256 threads
template<int MODE, int DOSILU, int ATTLAY>
__global__ void __launch_bounds__(256, 2) gemm_tc(
    const float* __restrict__ A, const float* __restrict__ W,
    const float* __restrict__ bias, float* __restrict__ C)
{
    extern __shared__ float sm[];
    const uint32_t sb = smem_u32(sm);
    const int t = threadIdx.x;
    const int lane = t & 31, wid = t >> 5;
    const int wm = wid >> 2, wn = wid & 3;     // 2 x 4 warp grid
    const int m0 = blockIdx.y * BM;
    const int n0 = blockIdx.x * BN;
    const int g = lane >> 2, tc = lane & 3;

    float acc[4][4][4];
#pragma unroll
    for (int i = 0; i < 4; ++i)
#pragma unroll
        for (int j = 0; j < 4; ++j)
#pragma unroll
            for (int e = 0; e < 4; ++e) acc[i][j][e] = 0.f;

    const float* Abase = A + (size_t)m0 * DDIM;
    const float* Wbase = W + (size_t)n0 * DDIM;

    auto load_chunk = [&](int stage, int kc) {
        const uint32_t abase = sb + (uint32_t)(stage * STAGE_FLOATS) * 4u;
        const uint32_t bbase = abase + A_FLOATS * 4u;
        const int k0 = kc * BKK;
#pragma unroll
        for (int i = 0; i < 4; ++i) {           // A: 1024 x 16B
            int idx = t + 256 * i;
            int row = idx >> 3, seg = idx & 7;
            cp16(abase + (uint32_t)(row * STRD + seg * 4) * 4u,
                 Abase + (size_t)row * DDIM + k0 + seg * 4);
        }
#pragma unroll
        for (int i = 0; i < 4; ++i) {           // B: 1024 x 16B
            int idx = t + 256 * i;
            int row = idx >> 3, seg = idx & 7;
            cp16(bbase + (uint32_t)(row * STRD + seg * 4) * 4u,
                 Wbase + (size_t)row * DDIM + k0 + seg * 4);
        }
    };

    // prologue
#pragma unroll
    for (int s = 0; s < GSTAGES; ++s) { load_chunk(s, s); cp_commit(); }

    int cur = 0;
    for (int kc = 0; kc < KCH; ++kc) {
        CP_WAIT(GSTAGES - 1);
        __syncthreads();

        const float* sA = sm + cur * STAGE_FLOATS;
        const float* sB = sA + A_FLOATS;

        if (MODE == 0) {
            // ---- tf32 m16n8k8 single-pass (R8-proven path) ----
#pragma unroll
            for (int ks = 0; ks < 4; ++ks) {
                const int k0 = ks * 8;
                uint32_t bh_[4][2];
#pragma unroll
                for (int nt = 0; nt < 4; ++nt) {
                    const float* p = sB + (wn * 32 + nt * 8 + g) * STRD + k0 + tc;
                    bh_[nt][0] = to_tf32(p[0]);
                    bh_[nt][1] = to_tf32(p[4]);
                }
#pragma unroll
                for (int mt = 0; mt < 4; ++mt) {
                    const float* p = sA + (wm * 64 + mt * 16 + g) * STRD + k0 + tc;
                    uint32_t ah[4];
                    ah[0] = to_tf32(p[0]);
                    ah[1] = to_tf32(p[8 * STRD]);
                    ah[2] = to_tf32(p[4]);
                    ah[3] = to_tf32(p[8 * STRD + 4]);
#pragma unroll
                    for (int nt = 0; nt < 4; ++nt)
                        mma8(acc[mt][nt], ah, bh_[nt]);
                }
            }
        } else {
            // ---- fp16 m16n8k16 (single or hi/lo split) ----
#pragma unroll
            for (int ks = 0; ks < 2; ++ks) {
                const int k0 = ks * 16;
                uint32_t bh_[4][2], bl_[4][2];
#pragma unroll
                for (int nt = 0; nt < 4; ++nt) {
                    const float* p = sB + (wn * 32 + nt * 8 + g) * STRD + k0 + 2 * tc;
                    float2 p0 = *(const float2*)p;
                    float2 p1 = *(const float2*)(p + 8);
                    if (MODE == 2) {
                        float h0, l0, h1, l1;
                        split_h(p0.x, h0, l0); split_h(p0.y, h1, l1);
                        bh_[nt][0] = packh2(h1, h0); bl_[nt][0] = packh2(l1, l0);
                        split_h(p1.x, h0, l0); split_h(p1.y, h1, l1);
                        bh_[nt][1] = packh2(h1, h0); bl_[nt][1] = packh2(l1, l0);
                    } else {
                        bh_[nt][0] = packh2(p0.y, p0.x);
                        bh_[nt][1] = packh2(p1.y, p1.x);
                    }
                }
#pragma unroll
                for (int mt = 0; mt < 4; ++mt) {
                    const float* p = sA + (wm * 64 + mt * 16 + g) * STRD + k0 + 2 * tc;
                    float2 q0 = *(const float2*)p;
                    float2 q1 = *(const float2*)(p + 8 * STRD);
                    float2 q2 = *(const float2*)(p + 8);
                    float2 q3 = *(const float2*)(p + 8 * STRD + 8);
                    uint32_t ah[4], al[4];
                    if (MODE == 2) {
                        float h0, l0, h1, l1;
                        split_h(q0.x, h0, l0); split_h(q0.y, h1, l1);
                        ah[0] = packh2(h1, h0); al[0] = packh2(l1, l0);
                        split_h(q1.x, h0, l0); split_h(q1.y, h1, l1);
                        ah[1] = packh2(h1, h0); al[1] = packh2(l1, l0);
                        split_h(q2.x, h0, l0); split_h(q2.y, h1, l1);
                        ah[2] = packh2(h1, h0); al[2] = packh2(l1, l0);
                        split_h(q3.x, h0, l0); split_h(q3.y, h1, l1);
                        ah[3] = packh2(h1, h0); al[3] = packh2(l1, l0);
#pragma unroll
                        for (int nt = 0; nt < 4; ++nt) {
                            mma16(acc[mt][nt], ah, bl_[nt]);   // h*l
                            mma16(acc[mt][nt], al, bh_[nt]);   // l*h
                            mma16(acc[mt][nt], ah, bh_[nt]);   // h*h
                        }
                    } else {
                        ah[0] = packh2(q0.y, q0.x);
                        ah[1] = packh2(q1.y, q1.x);
                        ah[2] = packh2(q2.y, q2.x);
                        ah[3] = packh2(q3.y, q3.x);
#pragma unroll
                        for (int nt = 0; nt < 4; ++nt)
                            mma16(acc[mt][nt], ah, bh_[nt]);
                    }
                }
            }
        }
        __syncthreads();

        if (kc + GSTAGES < KCH) load_chunk(cur, kc + GSTAGES);
        cp_commit();

        cur = (cur == GSTAGES - 1) ? 0 : cur + 1;
    }

    // ---- epilogue (same accumulator layout for both MMA shapes) ----
#pragma unroll
    for (int mt = 0; mt < 4; ++mt) {
        const int mrow = m0 + wm * 64 + mt * 16 + g;
#pragma unroll
        for (int nt = 0; nt < 4; ++nt) {
            const int n = n0 + wn * 32 + nt * 8 + tc * 2;
#pragma unroll
            for (int half = 0; half < 2; ++half) {
                const int m = mrow + half * 8;
                float v0 = acc[mt][nt][half * 2 + 0] + bias[n];
                float v1 = acc[mt][nt][half * 2 + 1] + bias[n + 1];
                if (DOSILU) {
                    v0 = v0 / (1.f + expf(-v0));
                    v1 = v1 / (1.f + expf(-v1));
                }
                float2 o; o.x = v0; o.y = v1;
                if (ATTLAY) {
                    int b  = m >> 11;
                    int l  = m & 2047;
                    int h  = n >> 6;
                    int dd = n & 63;
                    *(float2*)&C[(((size_t)(b * HH + h)) * LL + l) * DH + dd] = o;
                } else {
                    *(float2*)&C[(size_t)m * DDIM + n] = o;
                }
            }
        }
    }
}

// ---------------- Phase A: per-chunk kv outer product + ksum ----------------
__global__ __launch_bounds__(256) void chunk_stats()
{
    __shared__ float ks[32*64];
    __shared__ float vs[32*64];

    const int bid = blockIdx.x;
    const float* kb = g_k + (size_t)bid * (CH*DH);
    const float* vb = g_v + (size_t)bid * (CH*DH);
    const int t  = threadIdx.x;
    const int td = t >> 4;
    const int te = t & 15;

    float acc[4][4];
#pragma unroll
    for (int i = 0; i < 4; ++i)
#pragma unroll
        for (int j = 0; j < 4; ++j) acc[i][j] = 0.f;
    float zacc = 0.f;

    for (int cb = 0; cb < 4; ++cb) {
#pragma unroll
        for (int r = 0; r < 2; ++r) {
            int f = t*2 + r;
            *(float4*)&ks[f*4] = *(const float4*)(kb + cb*2048 + f*4);
            *(float4*)&vs[f*4] = *(const float4*)(vb + cb*2048 + f*4);
        }
        __syncthreads();
#pragma unroll 8
        for (int c = 0; c < 32; ++c) {
            float a[4], b[4];
            *(float4*)a = *(const float4*)&ks[c*64 + td*4];
            *(float4*)b = *(const float4*)&vs[c*64 + te*4];
#pragma unroll
            for (int i = 0; i < 4; ++i)
#pragma unroll
                for (int j = 0; j < 4; ++j)
                    acc[i][j] = fmaf(a[i], b[j], acc[i][j]);
        }
        if (t < 64) {
#pragma unroll 8
            for (int c = 0; c < 32; ++c) zacc += ks[c*64 + t];
        }
        __syncthreads();
    }

    float* Sp = g_S + (size_t)bid * (DH*DH);
#pragma unroll
    for (int i = 0; i < 4; ++i)
#pragma unroll
        for (int j = 0; j < 4; ++j)
            Sp[(td*4 + i)*DH + te*4 + j] = acc[i][j];
    if (t < 64) g_z[(size_t)bid*DH + t] = zacc;
}

// ---------------- Phase B: exclusive scan over chunks ----------------
__global__ __launch_bounds__(256) void scan_chunks()
{
    const int bh = blockIdx.x;
    const int t  = threadIdx.x;
    for (int idx = t; idx < DH*DH; idx += 256) {
        float accv = 0.f;
#pragma unroll
        for (int nn = 0; nn < NC; ++nn) {
            float* p = g_S + ((size_t)(bh*NC + nn))*(DH*DH) + idx;
            float tv = *p; *p = accv; accv += tv;
        }
    }
    if (t < DH) {
        float accv = 0.f;
#pragma unroll
        for (int nn = 0; nn < NC; ++nn) {
            float* p = g_z + ((size_t)(bh*NC + nn))*DH + t;
            float tv = *p; *p = accv; accv += tv;
        }
    }
}

// ---------------- Phase C: intra-chunk causal attention (512 threads) ----------------
#define SMEMC_FLOATS (64*136 + 64*136 + 128*64 + 64*64 + 64 + 128 + 128*132)
__global__ __launch_bounds__(512, 1) void intra_chunk()
{
    extern __shared__ float smc[];
    float* qT   = smc;                // [64][136]  (dd-major, padded)
    float* kT   = qT + 64*136;
    float* vs   = kT + 64*136;        // [128][64]
    float* Ss   = vs + 128*64;        // [64][64]
    float* zs   = Ss + 64*64;         // [64]
    float* rden = zs + 64;            // [128]
    float* ms   = rden + 128;         // [128][132]

    const int bid = blockIdx.x;
    const int t   = threadIdx.x;
    const float* qb = g_q + (size_t)bid * (CH*DH);
    const float* kb = g_k + (size_t)bid * (CH*DH);
    const float* vb = g_v + (size_t)bid * (CH*DH);

    {
        int dd = t & 63;
        int ih = t >> 6;              // 0..7
#pragma unroll 4
        for (int ii = 0; ii < 16; ++ii) {
            int i = ih*16 + ii;
            qT[dd*136 + i] = qb[i*DH + dd];
            kT[dd*136 + i] = kb[i*DH + dd];
        }
    }
#pragma unroll
    for (int r = 0; r < 4; ++r) {     // vs: 2048 float4
        int f = t + 512*r;
        *(float4*)&vs[f*4] = *(const float4*)(vb + f*4);
    }
    {
        const float* Sp = g_S + (size_t)bid * (DH*DH);
#pragma unroll
        for (int r = 0; r < 2; ++r) { // Ss: 1024 float4
            int f = t + 512*r;
            *(float4*)&Ss[f*4] = *(const float4*)(Sp + f*4);
        }
    }
    if (t < 64) zs[t] = g_z[(size_t)bid*DH + t];
    __syncthreads();

    // stage 1: scores, 8x4 tile per thread
    {
        const int ty = t >> 5, tx = t & 31;
        const int i0 = ty*8, j0 = tx*4;

        float acc[8][4];
#pragma unroll
        for (int i = 0; i < 8; ++i)
#pragma unroll
            for (int j = 0; j < 4; ++j) acc[i][j] = 0.f;

        if (j0 <= i0 + 7) {           // skip fully-masked tiles
#pragma unroll 4
            for (int c = 0; c < 64; ++c) {
                float a[8], b[4];
                *(float4*)(a)     = *(const float4*)&qT[c*136 + i0];
                *(float4*)(a + 4) = *(const float4*)&qT[c*136 + i0 + 4];
                *(float4*)(b)     = *(const float4*)&kT[c*136 + j0];
#pragma unroll
                for (int i = 0; i < 8; ++i)
#pragma unroll
                    for (int j = 0; j < 4; ++j)
                        acc[i][j] = fmaf(a[i], b[j], acc[i][j]);
            }
        }
#pragma unroll
        for (int i = 0; i < 8; ++i)
#pragma unroll
            for (int j = 0; j < 4; ++j)
                ms[(i0+i)*132 + j0 + j] = (j0 + j <= i0 + i) ? acc[i][j] : 0.f;
    }
    __syncthreads();

    // denominator per row = rowsum(masked scores) + q.z  (4 threads/row)
    if (t < 512) {
        const int i = t >> 2, part = t & 3;
        float s = 0.f;
        const int jb = part * 32;
#pragma unroll 8
        for (int j = 0; j < 32; ++j) s += ms[i*132 + jb + j];
        const int db = part * 16;
#pragma unroll 8
        for (int dd = 0; dd < 16; ++dd) s += qT[(db+dd)*136 + i] * zs[db+dd];
        s += __shfl_down_sync(0xFFFFFFFF, s, 2);
        s += __shfl_down_sync(0xFFFFFFFF, s, 1);
        if (part == 0) rden[i] = 1.f / fmaxf(s, 0.001f);
    }
    __syncthreads();

    // stage 2: out[i][e] = sum_j ms[i][j]*v[j][e] + sum_dd q[i][dd]*S[dd][e]
    {
        const int i0 = (t >> 4) * 4;      // 0..124
        const int e0 = (t & 15) * 4;      // 0..60
        float o[4][4];
#pragma unroll
        for (int i = 0; i < 4; ++i)
#pragma unroll
            for (int e = 0; e < 4; ++e) o[i][e] = 0.f;

#pragma unroll 4
        for (int j = 0; j < 128; ++j) {
            float vf[4];
            *(float4*)vf = *(const float4*)&vs[j*64 + e0];
#pragma unroll
            for (int i = 0; i < 4; ++i) {
                float mv = ms[(i0+i)*132 + j];
                o[i][0] = fmaf(mv, vf[0], o[i][0]);
                o[i][1] = fmaf(mv, vf[1], o[i][1]);
                o[i][2] = fmaf(mv, vf[2], o[i][2]);
                o[i][3] = fmaf(mv, vf[3], o[i][3]);
            }
        }
#pragma unroll 4
        for (int dd = 0; dd < 64; ++dd) {
            float sf[4];
            *(float4*)sf = *(const float4*)&Ss[dd*64 + e0];
#pragma unroll
            for (int i = 0; i < 4; ++i) {
                float qv = qT[dd*136 + i0 + i];
                o[i][0] = fmaf(qv, sf[0], o[i][0]);
                o[i][1] = fmaf(qv, sf[1], o[i][1]);
                o[i][2] = fmaf(qv, sf[2], o[i][2]);
                o[i][3] = fmaf(qv, sf[3], o[i][3]);
            }
        }

        const int bh = bid >> 4, n = bid & 15;
        const int b = bh >> 4, h = bh & 15;
#pragma unroll
        for (int i = 0; i < 4; ++i) {
            float rd = rden[i0 + i];
            int l = n*CH + i0 + i;
            float4 ov;
            ov.x = o[i][0] * rd; ov.y = o[i][1] * rd;
            ov.z = o[i][2] * rd; ov.w = o[i][3] * rd;
            *(float4*)&g_att[((size_t)(b*LL + l))*DDIM + h*DH + e0] = ov;
        }
    }
}

// ---------------- launch ----------------
extern "C" void kernel_launch(void* const* d_in, const int* in_sizes, int n_in,
                              void* d_out, int out_size)
{
    const float* x  = (const float*)d_in[0];
    const float* Wq = (const float*)d_in[1];
    const float* bq = (const float*)d_in[2];
    const float* Wk = (const float*)d_in[3];
    const float* bk = (const float*)d_in[4];
    const float* Wv = (const float*)d_in[5];
    const float* bv = (const float*)d_in[6];
    const float* Wo = (const float*)d_in[7];
    const float* bo = (const float*)d_in[8];
    float* out = (float*)d_out;

    float *qp, *kp, *vp, *attp;
    cudaGetSymbolAddress((void**)&qp,  g_q);
    cudaGetSymbolAddress((void**)&kp,  g_k);
    cudaGetSymbolAddress((void**)&vp,  g_v);
    cudaGetSymbolAddress((void**)&attp, g_att);

    cudaFuncSetAttribute(gemm_tc<2,1,1>, cudaFuncAttributeMaxDynamicSharedMemorySize,
                         SMEM_GEMM_BYTES);
    cudaFuncSetAttribute(gemm_tc<1,0,1>, cudaFuncAttributeMaxDynamicSharedMemorySize,
                         SMEM_GEMM_BYTES);
    cudaFuncSetAttribute(gemm_tc<0,0,0>, cudaFuncAttributeMaxDynamicSharedMemorySize,
                         SMEM_GEMM_BYTES);
    cudaFuncSetAttribute(intra_chunk, cudaFuncAttributeMaxDynamicSharedMemorySize,
                         SMEMC_FLOATS * (int)sizeof(float));

    // One-time stream/event setup (no device memory involved)
    static cudaStream_t sK = nullptr, sV = nullptr;
    static cudaEvent_t eFork, eV, eQ, eAtt;
    if (sK == nullptr) {
        cudaStreamCreateWithFlags(&sK, cudaStreamNonBlocking);
        cudaStreamCreateWithFlags(&sV, cudaStreamNonBlocking);
        cudaEventCreateWithFlags(&eFork, cudaEventDisableTiming);
        cudaEventCreateWithFlags(&eV,    cudaEventDisableTiming);
        cudaEventCreateWithFlags(&eQ,    cudaEventDisableTiming);
        cudaEventCreateWithFlags(&eAtt,  cudaEventDisableTiming);
    }

    dim3 gg(DDIM/BN, BLROWS/BM);   // (8, 64)
    dim3 bb(256);

    // Fork from the origin stream so sK/sV join the capture.
    cudaEventRecord(eFork, 0);
    cudaStreamWaitEvent(sK, eFork, 0);
    cudaStreamWaitEvent(sV, eFork, 0);

    // K, V issued first -> work distributor fills SMs with them first.
    gemm_tc<2,1,1><<<gg, bb, SMEM_GEMM_BYTES, sK>>>(x, Wk, bk, kp);
    gemm_tc<1,0,1><<<gg, bb, SMEM_GEMM_BYTES, sV>>>(x, Wv, bv, vp);
    cudaEventRecord(eV, sV);

    // Q on origin stream: starts as K/V drain; runs concurrent with stats/scan.
    gemm_tc<2,1,1><<<gg, bb, SMEM_GEMM_BYTES>>>(x, Wq, bq, qp);
    cudaEventRecord(eQ, 0);

    // stats+scan on sK after K (stream-ordered) and V (event).
    cudaStreamWaitEvent(sK, eV, 0);
    chunk_stats<<<BH*NC, 256, 0, sK>>>();
    scan_chunks<<<BH, 256, 0, sK>>>();

    // intra needs Q as well.
    cudaStreamWaitEvent(sK, eQ, 0);
    intra_chunk<<<BH*NC, 512, SMEMC_FLOATS * sizeof(float), sK>>>();
    cudaEventRecord(eAtt, sK);

    // Wo joins back on the origin stream (tf32 path — fp32 range for large att).
    cudaStreamWaitEvent(0, eAtt, 0);
    gemm_tc<0,0,0><<<gg, bb, SMEM_GEMM_BYTES>>>(attp, Wo, bo, out);
}